// round 16
// baseline (speedup 1.0000x reference)
#include <cuda_runtime.h>
#include <cuda_fp16.h>
#include <cstdint>

#define BDIM  1024
#define HEADS 16
#define HD    64
#define LSEQ  1024
#define BATCH 8
#define MROWS (BATCH * LSEQ)   // 8192
#define ACT_SZ  ((size_t)MROWS * BDIM)          // 8M halfs
#define WT_SZ   ((size_t)BDIM * BDIM)           // 1M halfs
#define QKV_SZ  ((size_t)BATCH * HEADS * LSEQ * HD)

// ---------------------------------------------------------------------------
// Scratch (__device__ globals; allocation-free rule)
// ---------------------------------------------------------------------------
__device__ __half g_act[3 * ACT_SZ];    // f16 query/key/value activations
__device__ __half g_wt[4 * WT_SZ];      // f16 Wq/Wk/Wv/Wp
__device__ __half g_qkv[3 * QKV_SZ];    // f16 Q/K/V in (B,H,L,hd)
__device__ __half g_y[ACT_SZ];          // f16 attention output (B,L,D)

// ---------------------------------------------------------------------------
// PTX helpers (base-target only)
// ---------------------------------------------------------------------------
__device__ __forceinline__ uint32_t smem_u32(const void* p) {
    uint32_t a;
    asm("{ .reg .u64 t; cvta.to.shared.u64 t, %1; cvt.u32.u64 %0, t; }" : "=r"(a) : "l"(p));
    return a;
}
__device__ __forceinline__ void ldmx4(uint32_t r[4], uint32_t a) {
    asm volatile("ldmatrix.sync.aligned.m8n8.x4.shared.b16 {%0,%1,%2,%3}, [%4];"
                 : "=r"(r[0]), "=r"(r[1]), "=r"(r[2]), "=r"(r[3]) : "r"(a));
}
__device__ __forceinline__ void ldmx4t(uint32_t r[4], uint32_t a) {
    asm volatile("ldmatrix.sync.aligned.m8n8.x4.trans.shared.b16 {%0,%1,%2,%3}, [%4];"
                 : "=r"(r[0]), "=r"(r[1]), "=r"(r[2]), "=r"(r[3]) : "r"(a));
}
__device__ __forceinline__ void mma_f16(float c[4], const uint32_t a[4],
                                        uint32_t b0, uint32_t b1) {
    asm volatile(
        "mma.sync.aligned.m16n8k16.row.col.f32.f16.f16.f32 "
        "{%0,%1,%2,%3}, {%4,%5,%6,%7}, {%8,%9}, {%0,%1,%2,%3};"
        : "+f"(c[0]), "+f"(c[1]), "+f"(c[2]), "+f"(c[3])
        : "r"(a[0]), "r"(a[1]), "r"(a[2]), "r"(a[3]), "r"(b0), "r"(b1));
}
__device__ __forceinline__ void cp16(uint32_t s, const void* g) {
    asm volatile("cp.async.cg.shared.global [%0], [%1], 16;" :: "r"(s), "l"(g));
}
__device__ __forceinline__ uint32_t pack2(float x, float y) {
    __half2 h = __floats2half2_rn(x, y);     // .x = low half = even element
    return *reinterpret_cast<uint32_t*>(&h);
}
__device__ __forceinline__ float ex2(float x) {
    float y;
    asm("ex2.approx.ftz.f32 %0, %1;" : "=f"(y) : "f"(x));
    return y;
}

// ---------------------------------------------------------------------------
// Batched fp32 -> fp16 converts: block-strided, 4 coalesced LDG.128 +
// 4 coalesced STG.64 per thread (MLP=4).
// ---------------------------------------------------------------------------
__global__ __launch_bounds__(256) void convert_acts(const float* __restrict__ q,
                                                    const float* __restrict__ k,
                                                    const float* __restrict__ v,
                                                    __half* __restrict__ dst) {
    const int t = blockIdx.y;
    const float* src = (t == 0) ? q : (t == 1) ? k : v;
    __half* d = dst + (size_t)t * ACT_SZ;
    const int base = blockIdx.x * 1024 + threadIdx.x;   // 4 float4 per thread
    const float4* s4 = reinterpret_cast<const float4*>(src);
    uint2* d2 = reinterpret_cast<uint2*>(d);
    float4 a0 = s4[base];
    float4 a1 = s4[base + 256];
    float4 a2 = s4[base + 512];
    float4 a3 = s4[base + 768];
    uint2 u0 = {pack2(a0.x, a0.y), pack2(a0.z, a0.w)};
    uint2 u1 = {pack2(a1.x, a1.y), pack2(a1.z, a1.w)};
    uint2 u2 = {pack2(a2.x, a2.y), pack2(a2.z, a2.w)};
    uint2 u3 = {pack2(a3.x, a3.y), pack2(a3.z, a3.w)};
    d2[base]       = u0;
    d2[base + 256] = u1;
    d2[base + 512] = u2;
    d2[base + 768] = u3;
}

__global__ __launch_bounds__(256) void convert_wts(const float* __restrict__ w0,
                                                   const float* __restrict__ w1,
                                                   const float* __restrict__ w2,
                                                   const float* __restrict__ w3,
                                                   __half* __restrict__ dst) {
    const int t = blockIdx.y;
    const float* src = (t == 0) ? w0 : (t == 1) ? w1 : (t == 2) ? w2 : w3;
    __half* d = dst + (size_t)t * WT_SZ;
    const int base = blockIdx.x * 1024 + threadIdx.x;
    const float4* s4 = reinterpret_cast<const float4*>(src);
    uint2* d2 = reinterpret_cast<uint2*>(d);
    float4 a0 = s4[base];
    float4 a1 = s4[base + 256];
    float4 a2 = s4[base + 512];
    float4 a3 = s4[base + 768];
    uint2 u0 = {pack2(a0.x, a0.y), pack2(a0.z, a0.w)};
    uint2 u1 = {pack2(a1.x, a1.y), pack2(a1.z, a1.w)};
    uint2 u2 = {pack2(a2.x, a2.y), pack2(a2.z, a2.w)};
    uint2 u3 = {pack2(a3.x, a3.y), pack2(a3.z, a3.w)};
    d2[base]       = u0;
    d2[base + 256] = u1;
    d2[base + 512] = u2;
    d2[base + 768] = u3;
}

// ---------------------------------------------------------------------------
// HMMA fp16 GEMM (frozen from Round 13): CTA 128x128, 4 warps of 64x64
// (128 threads), K-chunk 64, 3-stage cp.async pipeline, one sync per chunk,
// issue(c+2) targets retired buffer (c-1)%3.
// MODE 1: f16 out to (B,H,L,hd) (z in 0..2). MODE 0: fp32 out (M,N), z=0.
// ---------------------------------------------------------------------------
#define GP         144                   // pitch bytes (128 data + 16 pad)
#define GT_B       (128 * GP)            // 18432 per tile
#define GBUF_B     (2 * GT_B)            // 36864 per stage (A + W)
#define GEMM_SMEM  (3 * GBUF_B)          // 110592 (3 stages)
#define GTHREADS   128

template <int MODE>
__global__ __launch_bounds__(GTHREADS) void gemm_mma(const __half* __restrict__ A0,
                                                     const __half* __restrict__ W0,
                                                     const float* __restrict__ b0,
                                                     const float* __restrict__ b1,
                                                     const float* __restrict__ b2,
                                                     float* __restrict__ C,
                                                     __half* __restrict__ Ch0) {
    extern __shared__ char smem[];
    const uint32_t sbase = smem_u32(smem);
    const int tid = threadIdx.x;
    const int wid = tid >> 5;            // 0..3
    const int lane = tid & 31;
    const int z = blockIdx.z;
    const int m0 = blockIdx.y * 128;
    const int n0 = blockIdx.x * 128;

    const __half* A = A0 + (size_t)z * ACT_SZ;
    const __half* W = W0 + (size_t)z * WT_SZ;
    const float* bias = (z == 0) ? b0 : (z == 1) ? b1 : b2;
    __half* Ch = Ch0 + (size_t)z * QKV_SZ;

    const __half* srcs[2] = {A + (size_t)m0 * BDIM, W + (size_t)n0 * BDIM};

    // 2 tiles x 128 rows x 8 segs(16B) = 2048 cp16, 16 per thread
    auto issue = [&](int c) {
        const int koff = c * 64;
        const uint32_t dbase = sbase + (c % 3) * GBUF_B;
#pragma unroll
        for (int t = 0; t < 16; t++) {
            const int gid = t * GTHREADS + tid;
            const int tile = gid >> 10;
            const int id = gid & 1023;
            const int row = id >> 3;
            const int seg = id & 7;
            cp16(dbase + tile * GT_B + row * GP + seg * 16,
                 srcs[tile] + row * BDIM + koff + seg * 8);
        }
        asm volatile("cp.async.commit_group;");
    };

    const int warp_m = (wid >> 1) * 64;          // 0 or 64
    const int warp_n = (wid & 1) * 64;           // 0 or 64
    const int a_row = warp_m + (lane & 15);
    const int a_k8  = (lane >> 4) * 8;
    const int b_row = warp_n + (lane & 7) + ((lane >> 4) << 3);
    const int b_k8  = ((lane >> 3) & 1) * 8;

    float acc[4][8][4] = {};

    issue(0); issue(1);
    for (int c = 0; c < 16; c++) {
        if (c < 15) asm volatile("cp.async.wait_group 1;" ::: "memory");
        else        asm volatile("cp.async.wait_group 0;" ::: "memory");
        __syncthreads();
        const uint32_t bb = sbase + (c % 3) * GBUF_B;
        const uint32_t aB = bb;
        const uint32_t wB = bb + GT_B;
#pragma unroll
        for (int ks = 0; ks < 4; ks++) {
            const int kc = ks * 16;
            uint32_t ra[4][4];
#pragma unroll
            for (int mf = 0; mf < 4; mf++)
                ldmx4(ra[mf], aB + (a_row + mf * 16) * GP + (kc + a_k8) * 2);
            uint32_t rb[4][4];
#pragma unroll
            for (int nf2 = 0; nf2 < 4; nf2++)
                ldmx4(rb[nf2], wB + (b_row + nf2 * 16) * GP + (kc + b_k8) * 2);
#pragma unroll
            for (int mf = 0; mf < 4; mf++)
#pragma unroll
                for (int nf = 0; nf < 8; nf++)
                    mma_f16(acc[mf][nf], ra[mf],
                            rb[nf >> 1][(nf & 1) * 2], rb[nf >> 1][(nf & 1) * 2 + 1]);
        }
        if (c + 2 < 16) issue(c + 2);    // buffer (c-1)%3: retired above
    }

#pragma unroll
    for (int mf = 0; mf < 4; mf++) {
        const int mA = m0 + warp_m + mf * 16 + (lane >> 2);
#pragma unroll
        for (int nf = 0; nf < 8; nf++) {
            const int n = n0 + warp_n + nf * 8 + (lane & 3) * 2;
            const float2 bv = *reinterpret_cast<const float2*>(bias + n);
#pragma unroll
            for (int half = 0; half < 2; half++) {
                const int m = mA + half * 8;
                const float ox = acc[mf][nf][half * 2 + 0] + bv.x;
                const float oy = acc[mf][nf][half * 2 + 1] + bv.y;
                if (MODE == 1) {
                    const int b = m >> 10;
                    const int l = m & 1023;
                    const int h = n >> 6;
                    const int cc = n & 63;
                    const size_t idx = (size_t)(((b * HEADS + h) * LSEQ) + l) * HD + cc;
                    *reinterpret_cast<uint32_t*>(Ch + idx) = pack2(ox, oy);
                } else {
                    float2 out = {ox, oy};
                    *reinterpret_cast<float2*>(C + (size_t)m * BDIM + n) = out;
                }
            }
        }
    }
}

// ---------------------------------------------------------------------------
// HMMA fp16 flash attention (frozen from Round 12): Br=128, Bc=64, causal,
// fp32 softmax in exp2 domain, 3-stage KV pipeline, heavy CTAs first.
// ---------------------------------------------------------------------------
#define AP     144
#define QT_B   (128 * AP)               // 18432
#define KVT_B  (64 * AP)                // 9216
#define KVS_B  (2 * KVT_B)              // 18432 per stage (K + V)
#define ATTN_SMEM (QT_B + 3 * KVS_B)    // 73728
#define CLOG2  0.1803368801f            // 0.125 * log2(e)

__global__ __launch_bounds__(256) void attn_mma(
    const __half* __restrict__ qkv, __half* __restrict__ yf) {
    extern __shared__ char smem[];
    const uint32_t sb = smem_u32(smem);
    const int tid = threadIdx.x;
    const int wid = tid >> 5;
    const int lane = tid & 31;
    const int qt = gridDim.x - 1 - blockIdx.x;   // heavy tiles first
    const int bh = blockIdx.y;
    const size_t hoff = (size_t)bh * LSEQ * HD;

    const __half* qsrc = qkv + hoff;
    const __half* kvsrc[2] = {qkv + QKV_SZ + hoff, qkv + 2 * QKV_SZ + hoff};

    auto issue_kv = [&](int kt) {
        const uint32_t dbase = sb + QT_B + (kt % 3) * KVS_B;
#pragma unroll
        for (int t = 0; t < 4; t++) {
            const int gid = t * 256 + tid;
            const int tile = gid >> 9;       // 0 = K, 1 = V
            const int id = gid & 511;
            const int row = id >> 3;         // 0..63
            const int seg = id & 7;
            cp16(dbase + tile * KVT_B + row * AP + seg * 16,
                 kvsrc[tile] + (size_t)(kt * 64 + row) * HD + seg * 8);
        }
        asm volatile("cp.async.commit_group;");
    };

    // Q tile: committed with KV0 (group 0)
#pragma unroll
    for (int t = 0; t < 4; t++) {
        const int gid = t * 256 + tid;
        const int row = gid >> 3;
        const int seg = gid & 7;
        cp16(sb + row * AP + seg * 16,
             qsrc + (size_t)(qt * 128 + row) * HD + seg * 8);
    }
    issue_kv(0);
    const int ktmax = 2 * qt + 1;
    if (1 <= ktmax) issue_kv(1);

    const int a_row = wid * 16 + (lane & 15);
    const int a_k8  = (lane >> 4) * 8;
    const int b_row = (lane & 7) + ((lane >> 4) << 3);
    const int b_k8  = ((lane >> 3) & 1) * 8;
    const int v_row = lane & 15;
    const int v_c8  = (lane >> 4) * 8;

    uint32_t qh[4][4];
    float oacc[8][4] = {};
    float m0 = -1e30f, m1 = -1e30f, l0 = 0.0f, l1 = 0.0f;

    for (int kt = 0; kt <= ktmax; kt++) {
        if (kt < ktmax) asm volatile("cp.async.wait_group 1;" ::: "memory");
        else            asm volatile("cp.async.wait_group 0;" ::: "memory");
        __syncthreads();
        if (kt == 0) {
#pragma unroll
            for (int ks = 0; ks < 4; ks++)
                ldmx4(qh[ks], sb + a_row * AP + (ks * 16 + a_k8) * 2);
        }
        const bool skip = (kt * 64) > (qt * 128 + wid * 16 + 15);
        if (!skip) {
            const uint32_t kB = sb + QT_B + (kt % 3) * KVS_B;
            const uint32_t vB = kB + KVT_B;

            // ---- S = Q K^T (raw scores) ----
            float sacc[8][4] = {};
#pragma unroll
            for (int ks = 0; ks < 4; ks++) {
#pragma unroll
                for (int nf2 = 0; nf2 < 4; nf2++) {
                    uint32_t br[4];
                    ldmx4(br, kB + (nf2 * 16 + b_row) * AP + (ks * 16 + b_k8) * 2);
                    mma_f16(sacc[nf2 * 2],     qh[ks], br[0], br[1]);
                    mma_f16(sacc[nf2 * 2 + 1], qh[ks], br[2], br[3]);
                }
            }
            // ---- causal mask (raw domain) ----
            const int r0g = qt * 128 + wid * 16 + (lane >> 2);
            const bool need_mask = (kt * 64 + 63) > (qt * 128 + wid * 16);
            if (need_mask) {
#pragma unroll
                for (int nf = 0; nf < 8; nf++)
#pragma unroll
                    for (int c = 0; c < 4; c++) {
                        const int col = kt * 64 + nf * 8 + (lane & 3) * 2 + (c & 1);
                        const int row = r0g + ((c >> 1) ? 8 : 0);
                        if (col > row) sacc[nf][c] = -1e30f;
                    }
            }
            // ---- online softmax in exp2 domain ----
            float mx0 = -1e30f, mx1 = -1e30f;
#pragma unroll
            for (int nf = 0; nf < 8; nf++) {
                mx0 = fmaxf(mx0, fmaxf(sacc[nf][0], sacc[nf][1]));
                mx1 = fmaxf(mx1, fmaxf(sacc[nf][2], sacc[nf][3]));
            }
            mx0 = fmaxf(mx0, __shfl_xor_sync(0xffffffffu, mx0, 1));
            mx0 = fmaxf(mx0, __shfl_xor_sync(0xffffffffu, mx0, 2));
            mx1 = fmaxf(mx1, __shfl_xor_sync(0xffffffffu, mx1, 1));
            mx1 = fmaxf(mx1, __shfl_xor_sync(0xffffffffu, mx1, 2));
            const float nm0 = fmaxf(m0, mx0);
            const float nm1 = fmaxf(m1, mx1);
            const float c0 = ex2((m0 - nm0) * CLOG2);
            const float c1 = ex2((m1 - nm1) * CLOG2);
            const float nm0C = nm0 * CLOG2;
            const float nm1C = nm1 * CLOG2;
            float s0 = 0.0f, s1 = 0.0f;
#pragma unroll
            for (int nf = 0; nf < 8; nf++) {
                float p0 = ex2(fmaf(sacc[nf][0], CLOG2, -nm0C));
                float p1 = ex2(fmaf(sacc[nf][1], CLOG2, -nm0C));
                float p2 = ex2(fmaf(sacc[nf][2], CLOG2, -nm1C));
                float p3 = ex2(fmaf(sacc[nf][3], CLOG2, -nm1C));
                sacc[nf][0] = p0; sacc[nf][1] = p1; sacc[nf][2] = p2; sacc[nf][3] = p3;
                s0 += p0 + p1; s1 += p2 + p3;
            }
            s0 += __shfl_xor_sync(0xffffffffu, s0, 1);
            s0 += __shfl_xor_sync(0xffffffffu, s0, 2);
            s1 += __shfl_xor_sync(0xffffffffu, s1, 1);
            s1 += __shfl_xor_sync(0xffffffffu, s1, 2);
            l0 = l0 * c0 + s0;
            l1 = l1 * c1 + s1;
            m0 = nm0; m1 = nm1;
#pragma unroll
            for (int nf = 0; nf < 8; nf++) {
                oacc[nf][0] *= c0; oacc[nf][1] *= c0;
                oacc[nf][2] *= c1; oacc[nf][3] *= c1;
            }
            // ---- pack P A-fragments (f16) ----
            uint32_t ph[4][4];
#pragma unroll
            for (int kb = 0; kb < 4; kb++) {
                ph[kb][0] = pack2(sacc[2 * kb][0],     sacc[2 * kb][1]);
                ph[kb][1] = pack2(sacc[2 * kb][2],     sacc[2 * kb][3]);
                ph[kb][2] = pack2(sacc[2 * kb + 1][0], sacc[2 * kb + 1][1]);
                ph[kb][3] = pack2(sacc[2 * kb + 1][2], sacc[2 * kb + 1][3]);
            }
            // ---- O += P V ----
#pragma unroll
            for (int kb = 0; kb < 4; kb++) {
#pragma unroll
                for (int g = 0; g < 4; g++) {
                    uint32_t vr[4];
                    ldmx4t(vr, vB + (kb * 16 + v_row) * AP + (g * 16 + v_c8) * 2);
                    mma_f16(oacc[g * 2],     ph[kb], vr[0], vr[1]);
                    mma_f16(oacc[g * 2 + 1], ph[kb], vr[2], vr[3]);
                }
            }
        }
        if (kt + 2 <= ktmax) issue_kv(kt + 2);
    }

    // ---- normalize & write f16 to (B,L,D) ----
    const float inv0 = 1.0f / l0;
    const float inv1 = 1.0f / l1;
    const int b = bh >> 4;
    const int h = bh & 15;
    const int r0 = qt * 128 + wid * 16 + (lane >> 2);
#pragma unroll
    for (int nf = 0; nf < 8; nf++) {
        const int col = h * HD + nf * 8 + (lane & 3) * 2;
        *reinterpret_cast<uint32_t*>(yf + (size_t)(b * LSEQ + r0) * BDIM + col) =
            pack2(oacc[nf][0] * inv0, oacc[nf][1] * inv0);
        *reinterpret_cast<uint32_t*>(yf + (size_t)(b * LSEQ + r0 + 8) * BDIM + col) =
            pack2(oacc[nf][2] * inv1, oacc[nf][3] * inv1);
    }
}

// ---------------------------------------------------------------------------
extern "C" void kernel_launch(void* const* d_in, const int* in_sizes, int n_in,
                              void* d_out, int out_size) {
    const float* key   = (const float*)d_in[0];
    const float* value = (const float*)d_in[1];
    const float* query = (const float*)d_in[2];
    const float* Wk    = (const float*)d_in[3];
    const float* bk    = (const float*)d_in[4];
    const float* Wq    = (const float*)d_in[5];
    const float* bq    = (const float*)d_in[6];
    const float* Wv    = (const float*)d_in[7];
    const float* bv    = (const float*)d_in[8];
    const float* Wp    = (const float*)d_in[9];
    const float* bp    = (const float*)d_in[10];
    float* out = (float*)d_out;

    __half *act, *wt, *qkv, *yf;
    cudaGetSymbolAddress((void**)&act, g_act);
    cudaGetSymbolAddress((void**)&wt, g_wt);
    cudaGetSymbolAddress((void**)&qkv, g_qkv);
    cudaGetSymbolAddress((void**)&yf, g_y);

    cudaFuncSetAttribute(gemm_mma<1>, cudaFuncAttributeMaxDynamicSharedMemorySize, GEMM_SMEM);
    cudaFuncSetAttribute(gemm_mma<0>, cudaFuncAttributeMaxDynamicSharedMemorySize, GEMM_SMEM);
    cudaFuncSetAttribute(attn_mma, cudaFuncAttributeMaxDynamicSharedMemorySize, ATTN_SMEM);

    // Converts: block-strided, 1024 float4 per block
    const int nA4 = MROWS * BDIM / 4;   // 2097152
    const int nW4 = BDIM * BDIM / 4;    // 262144
    convert_acts<<<dim3(nA4 / 1024, 3), 256>>>(query, key, value, act);
    convert_wts<<<dim3(nW4 / 1024, 4), 256>>>(Wq, Wk, Wv, Wp, wt);

    // Fused Q/K/V projections (z = 0,1,2), 128 threads/CTA
    dim3 gG3(BDIM / 128, MROWS / 128, 3);
    gemm_mma<1><<<gG3, GTHREADS, GEMM_SMEM>>>(act, wt, bq, bk, bv, nullptr, qkv);

    // Attention -> yf (f16, (B,L,D))
    dim3 gA(LSEQ / 128, BATCH * HEADS);
    attn_mma<<<gA, 256, ATTN_SMEM>>>(qkv, yf);

    // Output projection (fp32 out); A = yf, W = wt[3]
    dim3 gG(BDIM / 128, MROWS / 128, 1);
    gemm_mma<0><<<gG, GTHREADS, GEMM_SMEM>>>(yf, wt + 3 * WT_SZ, bp, bp, bp, out, nullptr);
}

// round 17
// speedup vs baseline: 1.0127x; 1.0127x over previous
#include <cuda_runtime.h>
#include <cuda_fp16.h>
#include <cstdint>

#define BDIM  1024
#define HEADS 16
#define HD    64
#define LSEQ  1024
#define BATCH 8
#define MROWS (BATCH * LSEQ)   // 8192
#define ACT_SZ  ((size_t)MROWS * BDIM)          // 8M halfs
#define WT_SZ   ((size_t)BDIM * BDIM)           // 1M halfs
#define QKV_SZ  ((size_t)BATCH * HEADS * LSEQ * HD)

// ---------------------------------------------------------------------------
// Scratch (__device__ globals; allocation-free rule)
// ---------------------------------------------------------------------------
__device__ __half g_act[3 * ACT_SZ];    // f16 query/key/value activations
__device__ __half g_wt[4 * WT_SZ];      // f16 Wq/Wk/Wv/Wp
__device__ __half g_qkv[3 * QKV_SZ];    // f16 Q/K/V in (B,H,L,hd)
__device__ __half g_y[ACT_SZ];          // f16 attention output (B,L,D)

// ---------------------------------------------------------------------------
// PTX helpers (base-target only)
// ---------------------------------------------------------------------------
__device__ __forceinline__ uint32_t smem_u32(const void* p) {
    uint32_t a;
    asm("{ .reg .u64 t; cvta.to.shared.u64 t, %1; cvt.u32.u64 %0, t; }" : "=r"(a) : "l"(p));
    return a;
}
__device__ __forceinline__ void ldmx4(uint32_t r[4], uint32_t a) {
    asm volatile("ldmatrix.sync.aligned.m8n8.x4.shared.b16 {%0,%1,%2,%3}, [%4];"
                 : "=r"(r[0]), "=r"(r[1]), "=r"(r[2]), "=r"(r[3]) : "r"(a));
}
__device__ __forceinline__ void ldmx4t(uint32_t r[4], uint32_t a) {
    asm volatile("ldmatrix.sync.aligned.m8n8.x4.trans.shared.b16 {%0,%1,%2,%3}, [%4];"
                 : "=r"(r[0]), "=r"(r[1]), "=r"(r[2]), "=r"(r[3]) : "r"(a));
}
__device__ __forceinline__ void mma_f16(float c[4], const uint32_t a[4],
                                        uint32_t b0, uint32_t b1) {
    asm volatile(
        "mma.sync.aligned.m16n8k16.row.col.f32.f16.f16.f32 "
        "{%0,%1,%2,%3}, {%4,%5,%6,%7}, {%8,%9}, {%0,%1,%2,%3};"
        : "+f"(c[0]), "+f"(c[1]), "+f"(c[2]), "+f"(c[3])
        : "r"(a[0]), "r"(a[1]), "r"(a[2]), "r"(a[3]), "r"(b0), "r"(b1));
}
__device__ __forceinline__ void cp16(uint32_t s, const void* g) {
    asm volatile("cp.async.cg.shared.global [%0], [%1], 16;" :: "r"(s), "l"(g));
}
__device__ __forceinline__ uint32_t pack2(float x, float y) {
    __half2 h = __floats2half2_rn(x, y);     // .x = low half = even element
    return *reinterpret_cast<uint32_t*>(&h);
}
__device__ __forceinline__ float ex2(float x) {
    float y;
    asm("ex2.approx.ftz.f32 %0, %1;" : "=f"(y) : "f"(x));
    return y;
}

// ---------------------------------------------------------------------------
// Single merged fp32 -> fp16 convert launch:
// grid.y 0..2 = query/key/value (2048 x-blocks), 3..6 = Wq/Wk/Wv/Wp
// (256 x-blocks; surplus blocks exit). Body identical to R14/16 converts.
// ---------------------------------------------------------------------------
__global__ __launch_bounds__(256) void convert_all(const float* __restrict__ q,
                                                   const float* __restrict__ k,
                                                   const float* __restrict__ v,
                                                   const float* __restrict__ w0,
                                                   const float* __restrict__ w1,
                                                   const float* __restrict__ w2,
                                                   const float* __restrict__ w3,
                                                   __half* __restrict__ act,
                                                   __half* __restrict__ wt,
                                                   int nblkW) {
    const int t = blockIdx.y;
    const float* src;
    __half* d;
    if (t < 3) {
        src = (t == 0) ? q : (t == 1) ? k : v;
        d = act + (size_t)t * ACT_SZ;
    } else {
        if (blockIdx.x >= nblkW) return;
        const int w = t - 3;
        src = (w == 0) ? w0 : (w == 1) ? w1 : (w == 2) ? w2 : w3;
        d = wt + (size_t)w * WT_SZ;
    }
    const int base = blockIdx.x * 1024 + threadIdx.x;   // 4 float4 per thread
    const float4* s4 = reinterpret_cast<const float4*>(src);
    uint2* d2 = reinterpret_cast<uint2*>(d);
    float4 a0 = s4[base];
    float4 a1 = s4[base + 256];
    float4 a2 = s4[base + 512];
    float4 a3 = s4[base + 768];
    uint2 u0 = {pack2(a0.x, a0.y), pack2(a0.z, a0.w)};
    uint2 u1 = {pack2(a1.x, a1.y), pack2(a1.z, a1.w)};
    uint2 u2 = {pack2(a2.x, a2.y), pack2(a2.z, a2.w)};
    uint2 u3 = {pack2(a3.x, a3.y), pack2(a3.z, a3.w)};
    d2[base]       = u0;
    d2[base + 256] = u1;
    d2[base + 512] = u2;
    d2[base + 768] = u3;
}

// ---------------------------------------------------------------------------
// HMMA fp16 GEMM (frozen from Round 13): CTA 128x128, 4 warps of 64x64
// (128 threads), K-chunk 64, 3-stage cp.async pipeline, one sync per chunk,
// issue(c+2) targets retired buffer (c-1)%3.
// MODE 1: f16 out to (B,H,L,hd) (z in 0..2). MODE 0: fp32 out (M,N), z=0.
// ---------------------------------------------------------------------------
#define GP         144                   // pitch bytes (128 data + 16 pad)
#define GT_B       (128 * GP)            // 18432 per tile
#define GBUF_B     (2 * GT_B)            // 36864 per stage (A + W)
#define GEMM_SMEM  (3 * GBUF_B)          // 110592 (3 stages)
#define GTHREADS   128

template <int MODE>
__global__ __launch_bounds__(GTHREADS) void gemm_mma(const __half* __restrict__ A0,
                                                     const __half* __restrict__ W0,
                                                     const float* __restrict__ b0,
                                                     const float* __restrict__ b1,
                                                     const float* __restrict__ b2,
                                                     float* __restrict__ C,
                                                     __half* __restrict__ Ch0) {
    extern __shared__ char smem[];
    const uint32_t sbase = smem_u32(smem);
    const int tid = threadIdx.x;
    const int wid = tid >> 5;            // 0..3
    const int lane = tid & 31;
    const int z = blockIdx.z;
    const int m0 = blockIdx.y * 128;
    const int n0 = blockIdx.x * 128;

    const __half* A = A0 + (size_t)z * ACT_SZ;
    const __half* W = W0 + (size_t)z * WT_SZ;
    const float* bias = (z == 0) ? b0 : (z == 1) ? b1 : b2;
    __half* Ch = Ch0 + (size_t)z * QKV_SZ;

    const __half* srcs[2] = {A + (size_t)m0 * BDIM, W + (size_t)n0 * BDIM};

    // 2 tiles x 128 rows x 8 segs(16B) = 2048 cp16, 16 per thread
    auto issue = [&](int c) {
        const int koff = c * 64;
        const uint32_t dbase = sbase + (c % 3) * GBUF_B;
#pragma unroll
        for (int t = 0; t < 16; t++) {
            const int gid = t * GTHREADS + tid;
            const int tile = gid >> 10;
            const int id = gid & 1023;
            const int row = id >> 3;
            const int seg = id & 7;
            cp16(dbase + tile * GT_B + row * GP + seg * 16,
                 srcs[tile] + row * BDIM + koff + seg * 8);
        }
        asm volatile("cp.async.commit_group;");
    };

    const int warp_m = (wid >> 1) * 64;          // 0 or 64
    const int warp_n = (wid & 1) * 64;           // 0 or 64
    const int a_row = warp_m + (lane & 15);
    const int a_k8  = (lane >> 4) * 8;
    const int b_row = warp_n + (lane & 7) + ((lane >> 4) << 3);
    const int b_k8  = ((lane >> 3) & 1) * 8;

    float acc[4][8][4] = {};

    issue(0); issue(1);
    for (int c = 0; c < 16; c++) {
        if (c < 15) asm volatile("cp.async.wait_group 1;" ::: "memory");
        else        asm volatile("cp.async.wait_group 0;" ::: "memory");
        __syncthreads();
        const uint32_t bb = sbase + (c % 3) * GBUF_B;
        const uint32_t aB = bb;
        const uint32_t wB = bb + GT_B;
#pragma unroll
        for (int ks = 0; ks < 4; ks++) {
            const int kc = ks * 16;
            uint32_t ra[4][4];
#pragma unroll
            for (int mf = 0; mf < 4; mf++)
                ldmx4(ra[mf], aB + (a_row + mf * 16) * GP + (kc + a_k8) * 2);
            uint32_t rb[4][4];
#pragma unroll
            for (int nf2 = 0; nf2 < 4; nf2++)
                ldmx4(rb[nf2], wB + (b_row + nf2 * 16) * GP + (kc + b_k8) * 2);
#pragma unroll
            for (int mf = 0; mf < 4; mf++)
#pragma unroll
                for (int nf = 0; nf < 8; nf++)
                    mma_f16(acc[mf][nf], ra[mf],
                            rb[nf >> 1][(nf & 1) * 2], rb[nf >> 1][(nf & 1) * 2 + 1]);
        }
        if (c + 2 < 16) issue(c + 2);    // buffer (c-1)%3: retired above
    }

#pragma unroll
    for (int mf = 0; mf < 4; mf++) {
        const int mA = m0 + warp_m + mf * 16 + (lane >> 2);
#pragma unroll
        for (int nf = 0; nf < 8; nf++) {
            const int n = n0 + warp_n + nf * 8 + (lane & 3) * 2;
            const float2 bv = *reinterpret_cast<const float2*>(bias + n);
#pragma unroll
            for (int half = 0; half < 2; half++) {
                const int m = mA + half * 8;
                const float ox = acc[mf][nf][half * 2 + 0] + bv.x;
                const float oy = acc[mf][nf][half * 2 + 1] + bv.y;
                if (MODE == 1) {
                    const int b = m >> 10;
                    const int l = m & 1023;
                    const int h = n >> 6;
                    const int cc = n & 63;
                    const size_t idx = (size_t)(((b * HEADS + h) * LSEQ) + l) * HD + cc;
                    *reinterpret_cast<uint32_t*>(Ch + idx) = pack2(ox, oy);
                } else {
                    float2 out = {ox, oy};
                    *reinterpret_cast<float2*>(C + (size_t)m * BDIM + n) = out;
                }
            }
        }
    }
}

// ---------------------------------------------------------------------------
// HMMA fp16 flash attention (frozen from Round 12): Br=128, Bc=64, causal,
// fp32 softmax in exp2 domain, 3-stage KV pipeline, heavy CTAs first.
// ---------------------------------------------------------------------------
#define AP     144
#define QT_B   (128 * AP)               // 18432
#define KVT_B  (64 * AP)                // 9216
#define KVS_B  (2 * KVT_B)              // 18432 per stage (K + V)
#define ATTN_SMEM (QT_B + 3 * KVS_B)    // 73728
#define CLOG2  0.1803368801f            // 0.125 * log2(e)

__global__ __launch_bounds__(256) void attn_mma(
    const __half* __restrict__ qkv, __half* __restrict__ yf) {
    extern __shared__ char smem[];
    const uint32_t sb = smem_u32(smem);
    const int tid = threadIdx.x;
    const int wid = tid >> 5;
    const int lane = tid & 31;
    const int qt = gridDim.x - 1 - blockIdx.x;   // heavy tiles first
    const int bh = blockIdx.y;
    const size_t hoff = (size_t)bh * LSEQ * HD;

    const __half* qsrc = qkv + hoff;
    const __half* kvsrc[2] = {qkv + QKV_SZ + hoff, qkv + 2 * QKV_SZ + hoff};

    auto issue_kv = [&](int kt) {
        const uint32_t dbase = sb + QT_B + (kt % 3) * KVS_B;
#pragma unroll
        for (int t = 0; t < 4; t++) {
            const int gid = t * 256 + tid;
            const int tile = gid >> 9;       // 0 = K, 1 = V
            const int id = gid & 511;
            const int row = id >> 3;         // 0..63
            const int seg = id & 7;
            cp16(dbase + tile * KVT_B + row * AP + seg * 16,
                 kvsrc[tile] + (size_t)(kt * 64 + row) * HD + seg * 8);
        }
        asm volatile("cp.async.commit_group;");
    };

    // Q tile: committed with KV0 (group 0)
#pragma unroll
    for (int t = 0; t < 4; t++) {
        const int gid = t * 256 + tid;
        const int row = gid >> 3;
        const int seg = gid & 7;
        cp16(sb + row * AP + seg * 16,
             qsrc + (size_t)(qt * 128 + row) * HD + seg * 8);
    }
    issue_kv(0);
    const int ktmax = 2 * qt + 1;
    if (1 <= ktmax) issue_kv(1);

    const int a_row = wid * 16 + (lane & 15);
    const int a_k8  = (lane >> 4) * 8;
    const int b_row = (lane & 7) + ((lane >> 4) << 3);
    const int b_k8  = ((lane >> 3) & 1) * 8;
    const int v_row = lane & 15;
    const int v_c8  = (lane >> 4) * 8;

    uint32_t qh[4][4];
    float oacc[8][4] = {};
    float m0 = -1e30f, m1 = -1e30f, l0 = 0.0f, l1 = 0.0f;

    for (int kt = 0; kt <= ktmax; kt++) {
        if (kt < ktmax) asm volatile("cp.async.wait_group 1;" ::: "memory");
        else            asm volatile("cp.async.wait_group 0;" ::: "memory");
        __syncthreads();
        if (kt == 0) {
#pragma unroll
            for (int ks = 0; ks < 4; ks++)
                ldmx4(qh[ks], sb + a_row * AP + (ks * 16 + a_k8) * 2);
        }
        const bool skip = (kt * 64) > (qt * 128 + wid * 16 + 15);
        if (!skip) {
            const uint32_t kB = sb + QT_B + (kt % 3) * KVS_B;
            const uint32_t vB = kB + KVT_B;

            // ---- S = Q K^T (raw scores) ----
            float sacc[8][4] = {};
#pragma unroll
            for (int ks = 0; ks < 4; ks++) {
#pragma unroll
                for (int nf2 = 0; nf2 < 4; nf2++) {
                    uint32_t br[4];
                    ldmx4(br, kB + (nf2 * 16 + b_row) * AP + (ks * 16 + b_k8) * 2);
                    mma_f16(sacc[nf2 * 2],     qh[ks], br[0], br[1]);
                    mma_f16(sacc[nf2 * 2 + 1], qh[ks], br[2], br[3]);
                }
            }
            // ---- causal mask (raw domain) ----
            const int r0g = qt * 128 + wid * 16 + (lane >> 2);
            const bool need_mask = (kt * 64 + 63) > (qt * 128 + wid * 16);
            if (need_mask) {
#pragma unroll
                for (int nf = 0; nf < 8; nf++)
#pragma unroll
                    for (int c = 0; c < 4; c++) {
                        const int col = kt * 64 + nf * 8 + (lane & 3) * 2 + (c & 1);
                        const int row = r0g + ((c >> 1) ? 8 : 0);
                        if (col > row) sacc[nf][c] = -1e30f;
                    }
            }
            // ---- online softmax in exp2 domain ----
            float mx0 = -1e30f, mx1 = -1e30f;
#pragma unroll
            for (int nf = 0; nf < 8; nf++) {
                mx0 = fmaxf(mx0, fmaxf(sacc[nf][0], sacc[nf][1]));
                mx1 = fmaxf(mx1, fmaxf(sacc[nf][2], sacc[nf][3]));
            }
            mx0 = fmaxf(mx0, __shfl_xor_sync(0xffffffffu, mx0, 1));
            mx0 = fmaxf(mx0, __shfl_xor_sync(0xffffffffu, mx0, 2));
            mx1 = fmaxf(mx1, __shfl_xor_sync(0xffffffffu, mx1, 1));
            mx1 = fmaxf(mx1, __shfl_xor_sync(0xffffffffu, mx1, 2));
            const float nm0 = fmaxf(m0, mx0);
            const float nm1 = fmaxf(m1, mx1);
            const float c0 = ex2((m0 - nm0) * CLOG2);
            const float c1 = ex2((m1 - nm1) * CLOG2);
            const float nm0C = nm0 * CLOG2;
            const float nm1C = nm1 * CLOG2;
            float s0 = 0.0f, s1 = 0.0f;
#pragma unroll
            for (int nf = 0; nf < 8; nf++) {
                float p0 = ex2(fmaf(sacc[nf][0], CLOG2, -nm0C));
                float p1 = ex2(fmaf(sacc[nf][1], CLOG2, -nm0C));
                float p2 = ex2(fmaf(sacc[nf][2], CLOG2, -nm1C));
                float p3 = ex2(fmaf(sacc[nf][3], CLOG2, -nm1C));
                sacc[nf][0] = p0; sacc[nf][1] = p1; sacc[nf][2] = p2; sacc[nf][3] = p3;
                s0 += p0 + p1; s1 += p2 + p3;
            }
            s0 += __shfl_xor_sync(0xffffffffu, s0, 1);
            s0 += __shfl_xor_sync(0xffffffffu, s0, 2);
            s1 += __shfl_xor_sync(0xffffffffu, s1, 1);
            s1 += __shfl_xor_sync(0xffffffffu, s1, 2);
            l0 = l0 * c0 + s0;
            l1 = l1 * c1 + s1;
            m0 = nm0; m1 = nm1;
#pragma unroll
            for (int nf = 0; nf < 8; nf++) {
                oacc[nf][0] *= c0; oacc[nf][1] *= c0;
                oacc[nf][2] *= c1; oacc[nf][3] *= c1;
            }
            // ---- pack P A-fragments (f16) ----
            uint32_t ph[4][4];
#pragma unroll
            for (int kb = 0; kb < 4; kb++) {
                ph[kb][0] = pack2(sacc[2 * kb][0],     sacc[2 * kb][1]);
                ph[kb][1] = pack2(sacc[2 * kb][2],     sacc[2 * kb][3]);
                ph[kb][2] = pack2(sacc[2 * kb + 1][0], sacc[2 * kb + 1][1]);
                ph[kb][3] = pack2(sacc[2 * kb + 1][2], sacc[2 * kb + 1][3]);
            }
            // ---- O += P V ----
#pragma unroll
            for (int kb = 0; kb < 4; kb++) {
#pragma unroll
                for (int g = 0; g < 4; g++) {
                    uint32_t vr[4];
                    ldmx4t(vr, vB + (kb * 16 + v_row) * AP + (g * 16 + v_c8) * 2);
                    mma_f16(oacc[g * 2],     ph[kb], vr[0], vr[1]);
                    mma_f16(oacc[g * 2 + 1], ph[kb], vr[2], vr[3]);
                }
            }
        }
        if (kt + 2 <= ktmax) issue_kv(kt + 2);
    }

    // ---- normalize & write f16 to (B,L,D) ----
    const float inv0 = 1.0f / l0;
    const float inv1 = 1.0f / l1;
    const int b = bh >> 4;
    const int h = bh & 15;
    const int r0 = qt * 128 + wid * 16 + (lane >> 2);
#pragma unroll
    for (int nf = 0; nf < 8; nf++) {
        const int col = h * HD + nf * 8 + (lane & 3) * 2;
        *reinterpret_cast<uint32_t*>(yf + (size_t)(b * LSEQ + r0) * BDIM + col) =
            pack2(oacc[nf][0] * inv0, oacc[nf][1] * inv0);
        *reinterpret_cast<uint32_t*>(yf + (size_t)(b * LSEQ + r0 + 8) * BDIM + col) =
            pack2(oacc[nf][2] * inv1, oacc[nf][3] * inv1);
    }
}

// ---------------------------------------------------------------------------
extern "C" void kernel_launch(void* const* d_in, const int* in_sizes, int n_in,
                              void* d_out, int out_size) {
    const float* key   = (const float*)d_in[0];
    const float* value = (const float*)d_in[1];
    const float* query = (const float*)d_in[2];
    const float* Wk    = (const float*)d_in[3];
    const float* bk    = (const float*)d_in[4];
    const float* Wq    = (const float*)d_in[5];
    const float* bq    = (const float*)d_in[6];
    const float* Wv    = (const float*)d_in[7];
    const float* bv    = (const float*)d_in[8];
    const float* Wp    = (const float*)d_in[9];
    const float* bp    = (const float*)d_in[10];
    float* out = (float*)d_out;

    __half *act, *wt, *qkv, *yf;
    cudaGetSymbolAddress((void**)&act, g_act);
    cudaGetSymbolAddress((void**)&wt, g_wt);
    cudaGetSymbolAddress((void**)&qkv, g_qkv);
    cudaGetSymbolAddress((void**)&yf, g_y);

    cudaFuncSetAttribute(gemm_mma<1>, cudaFuncAttributeMaxDynamicSharedMemorySize, GEMM_SMEM);
    cudaFuncSetAttribute(gemm_mma<0>, cudaFuncAttributeMaxDynamicSharedMemorySize, GEMM_SMEM);
    cudaFuncSetAttribute(attn_mma, cudaFuncAttributeMaxDynamicSharedMemorySize, ATTN_SMEM);

    // One merged convert launch: acts (y=0..2, 2048 blocks), wts (y=3..6, 256)
    const int nblkA = MROWS * BDIM / 4 / 1024;   // 2048
    const int nblkW = BDIM * BDIM / 4 / 1024;    // 256
    convert_all<<<dim3(nblkA, 7), 256>>>(query, key, value, Wq, Wk, Wv, Wp,
                                         act, wt, nblkW);

    // Fused Q/K/V projections (z = 0,1,2), 128 threads/CTA
    dim3 gG3(BDIM / 128, MROWS / 128, 3);
    gemm_mma<1><<<gG3, GTHREADS, GEMM_SMEM>>>(act, wt, bq, bk, bv, nullptr, qkv);

    // Attention -> yf (f16, (B,L,D))
    dim3 gA(LSEQ / 128, BATCH * HEADS);
    attn_mma<<<gA, 256, ATTN_SMEM>>>(qkv, yf);

    // Output projection (fp32 out); A = yf, W = wt[3]
    dim3 gG(BDIM / 128, MROWS / 128, 1);
    gemm_mma<0><<<gG, GTHREADS, GEMM_SMEM>>>(yf, wt + 3 * WT_SZ, bp, bp, bp, out, nullptr);
}